// round 4
// baseline (speedup 1.0000x reference)
#include <cuda_runtime.h>

// Problem-fixed shapes
#define NN 50000
#define EE 800000
#define TT (EE + NN)      // real edges + self loops
#define H1 3
#define D1 192            // 3 heads x 64
#define D2 64
#define NG 128
#define ENC_NEG_INF 0x007FFFFFu

// ---------------- scratch (device globals; no runtime allocation) -----------
__device__ float    g_xp1[(size_t)NN * D1];   // layer1 lin output, later h1=elu(out1+b1)
__device__ float    g_out1[(size_t)NN * D1];
__device__ float    g_asrc1[NN * H1];
__device__ float    g_adst1[NN * H1];
__device__ unsigned g_amax1[NN * H1];
__device__ float    g_den1[NN * H1];
__device__ float    g_ex1[(size_t)TT * H1];   // alpha, then exp(alpha-amax)
__device__ float    g_xp2[(size_t)NN * D2];
__device__ float    g_out2[(size_t)NN * D2];
__device__ float    g_asrc2[NN];
__device__ float    g_adst2[NN];
__device__ unsigned g_amax2[NN];
__device__ float    g_den2[NN];
__device__ float    g_ex2[TT];
__device__ float    g_pool[NG * D2];
__device__ float    g_cnt[NG];

// ---------------- helpers ----------------------------------------------------
__device__ __forceinline__ unsigned fenc(float f) {
    unsigned u = __float_as_uint(f);
    return u ^ ((u & 0x80000000u) ? 0xFFFFFFFFu : 0x80000000u);
}
__device__ __forceinline__ float fdec(unsigned u) {
    u ^= ((u & 0x80000000u) ? 0x80000000u : 0xFFFFFFFFu);
    return __uint_as_float(u);
}
__device__ __forceinline__ void red4(float4* p, float4 v) {
    asm volatile("red.global.add.v4.f32 [%0], {%1,%2,%3,%4};"
                 :: "l"(p), "f"(v.x), "f"(v.y), "f"(v.z), "f"(v.w) : "memory");
}
__device__ __forceinline__ float warp_sum(float s) {
    #pragma unroll
    for (int o = 16; o; o >>= 1) s += __shfl_xor_sync(0xFFFFFFFFu, s, o);
    return s;
}

// ---------------- init: zero accumulators, set -inf max ----------------------
__global__ void k_init() {
    size_t i0 = (size_t)blockIdx.x * blockDim.x + threadIdx.x;
    size_t st = (size_t)gridDim.x * blockDim.x;
    for (size_t i = i0; i < (size_t)NN * D1; i += st) g_out1[i] = 0.f;
    for (size_t i = i0; i < (size_t)NN * D2; i += st) g_out2[i] = 0.f;
    for (size_t i = i0; i < (size_t)NN * H1; i += st) { g_den1[i] = 0.f; g_amax1[i] = ENC_NEG_INF; }
    for (size_t i = i0; i < (size_t)NN;      i += st) { g_den2[i] = 0.f; g_amax2[i] = ENC_NEG_INF; }
    for (size_t i = i0; i < (size_t)NG * D2; i += st) g_pool[i] = 0.f;
    for (size_t i = i0; i < (size_t)NG;      i += st) g_cnt[i] = 0.f;
}

// ---------------- GEMM1: xp1 = x @ W1   (16 rows/block, 192 threads) ---------
__global__ void k_gemm1(const float* __restrict__ x, const float* __restrict__ W1) {
    __shared__ float xs[16][128];
    int r0 = blockIdx.x * 16;
    int t = threadIdx.x;   // 0..191 = output column
    for (int i = t; i < 16 * 128; i += 192) {
        int r = i >> 7, c = i & 127;
        xs[r][c] = (r0 + r < NN) ? x[(size_t)(r0 + r) * 128 + c] : 0.f;
    }
    __syncthreads();
    float acc[16];
    #pragma unroll
    for (int r = 0; r < 16; r++) acc[r] = 0.f;
    #pragma unroll 4
    for (int k = 0; k < 128; k++) {
        float w = W1[k * 192 + t];
        #pragma unroll
        for (int r = 0; r < 16; r++) acc[r] = fmaf(xs[r][k], w, acc[r]);
    }
    #pragma unroll
    for (int r = 0; r < 16; r++)
        if (r0 + r < NN) g_xp1[(size_t)(r0 + r) * 192 + t] = acc[r];
}

// ---------------- attention dot products, layer 1 (warp per node-head) ------
__global__ void k_att1(const float* __restrict__ att_src, const float* __restrict__ att_dst) {
    int idx = blockIdx.x * 8 + (threadIdx.x >> 5);
    if (idx >= NN * H1) return;
    int lane = threadIdx.x & 31;
    int n = idx / 3, h = idx % 3;
    size_t base = (size_t)n * 192 + h * 64;
    float v0 = g_xp1[base + lane], v1 = g_xp1[base + 32 + lane];
    float ss = v0 * att_src[h * 64 + lane] + v1 * att_src[h * 64 + 32 + lane];
    float sd = v0 * att_dst[h * 64 + lane] + v1 * att_dst[h * 64 + 32 + lane];
    ss = warp_sum(ss); sd = warp_sum(sd);
    if (lane == 0) { g_asrc1[idx] = ss; g_adst1[idx] = sd; }
}

// ---------------- layer1 edge passes -----------------------------------------
__global__ void k_max1(const int* __restrict__ srcp, const int* __restrict__ dstp, int Ereal, int Etot) {
    int e = blockIdx.x * blockDim.x + threadIdx.x;
    if (e >= Etot) return;
    int s, d;
    if (e < Ereal) { s = __ldg(srcp + e); d = __ldg(dstp + e); } else { s = d = e - Ereal; }
    #pragma unroll
    for (int h = 0; h < 3; h++) {
        float a = g_asrc1[s * 3 + h] + g_adst1[d * 3 + h];
        a = fmaxf(a, 0.2f * a);                 // leaky_relu(0.2)
        g_ex1[(size_t)e * 3 + h] = a;
        atomicMax(&g_amax1[d * 3 + h], fenc(a));
    }
}

__global__ void k_exp1(const int* __restrict__ dstp, int Ereal, int Etot) {
    int e = blockIdx.x * blockDim.x + threadIdx.x;
    if (e >= Etot) return;
    int d = (e < Ereal) ? __ldg(dstp + e) : (e - Ereal);
    #pragma unroll
    for (int h = 0; h < 3; h++) {
        float a = g_ex1[(size_t)e * 3 + h];
        float ex = __expf(a - fdec(g_amax1[d * 3 + h]));
        g_ex1[(size_t)e * 3 + h] = ex;
        atomicAdd(&g_den1[d * 3 + h], ex);
    }
}

// warp per edge: scatter xp1[src]*coef into out1[dst] (48 float4 = 192 floats)
__global__ void k_agg1(const int* __restrict__ srcp, const int* __restrict__ dstp, int Ereal, int Etot) {
    int w = (blockIdx.x * blockDim.x + threadIdx.x) >> 5;
    if (w >= Etot) return;
    int lane = threadIdx.x & 31;
    int s, d;
    if (w < Ereal) { s = __ldg(srcp + w); d = __ldg(dstp + w); } else { s = d = w - Ereal; }
    const float4* xs = (const float4*)(g_xp1 + (size_t)s * 192);
    float4* od = (float4*)(g_out1 + (size_t)d * 192);
    int h0 = lane >> 4;   // float4 idx 'lane' covers cols [4*lane,4*lane+4) -> head lane/16
    float c0 = g_ex1[(size_t)w * 3 + h0] / fmaxf(g_den1[d * 3 + h0], 1e-16f);
    float4 v = xs[lane];
    v.x *= c0; v.y *= c0; v.z *= c0; v.w *= c0;
    red4(&od[lane], v);
    if (lane < 16) {
        float c2 = g_ex1[(size_t)w * 3 + 2] / fmaxf(g_den1[d * 3 + 2], 1e-16f);
        float4 v2 = xs[32 + lane];
        v2.x *= c2; v2.y *= c2; v2.z *= c2; v2.w *= c2;
        red4(&od[32 + lane], v2);
    }
}

// ---------------- h1 = elu(out1 + b1) -> g_xp1 --------------------------------
__global__ void k_bias_elu(const float* __restrict__ b1) {
    int n = blockIdx.x, t = threadIdx.x;   // 192 threads
    float v = g_out1[(size_t)n * 192 + t] + b1[t];
    g_xp1[(size_t)n * 192 + t] = v > 0.f ? v : expm1f(v);
}

// ---------------- GEMM2: xp2 = h1 @ W2  (32 rows/block, 128 threads) ---------
__global__ void k_gemm2(const float* __restrict__ W2) {
    __shared__ float xs[32][192];
    int r0 = blockIdx.x * 32;
    int t = threadIdx.x;           // 0..127
    for (int i = t; i < 32 * 192; i += 128) {
        int r = i / 192, c = i % 192;
        xs[r][c] = (r0 + r < NN) ? g_xp1[(size_t)(r0 + r) * 192 + c] : 0.f;
    }
    __syncthreads();
    int col = t & 63, grp = t >> 6;   // grp selects rows [grp*16, grp*16+16)
    float acc[16];
    #pragma unroll
    for (int r = 0; r < 16; r++) acc[r] = 0.f;
    #pragma unroll 4
    for (int k = 0; k < 192; k++) {
        float w = W2[k * 64 + col];
        #pragma unroll
        for (int r = 0; r < 16; r++) acc[r] = fmaf(xs[grp * 16 + r][k], w, acc[r]);
    }
    #pragma unroll
    for (int r = 0; r < 16; r++) {
        int nr = r0 + grp * 16 + r;
        if (nr < NN) g_xp2[(size_t)nr * 64 + col] = acc[r];
    }
}

// ---------------- attention dots, layer 2 (warp per node) --------------------
__global__ void k_att2(const float* __restrict__ att_src, const float* __restrict__ att_dst) {
    int n = blockIdx.x * 8 + (threadIdx.x >> 5);
    if (n >= NN) return;
    int lane = threadIdx.x & 31;
    size_t base = (size_t)n * 64;
    float v0 = g_xp2[base + lane], v1 = g_xp2[base + 32 + lane];
    float ss = v0 * att_src[lane] + v1 * att_src[32 + lane];
    float sd = v0 * att_dst[lane] + v1 * att_dst[32 + lane];
    ss = warp_sum(ss); sd = warp_sum(sd);
    if (lane == 0) { g_asrc2[n] = ss; g_adst2[n] = sd; }
}

// ---------------- layer2 edge passes -----------------------------------------
__global__ void k_max2(const int* __restrict__ srcp, const int* __restrict__ dstp, int Ereal, int Etot) {
    int e = blockIdx.x * blockDim.x + threadIdx.x;
    if (e >= Etot) return;
    int s, d;
    if (e < Ereal) { s = __ldg(srcp + e); d = __ldg(dstp + e); } else { s = d = e - Ereal; }
    float a = g_asrc2[s] + g_adst2[d];
    a = fmaxf(a, 0.2f * a);
    g_ex2[e] = a;
    atomicMax(&g_amax2[d], fenc(a));
}

__global__ void k_exp2(const int* __restrict__ dstp, int Ereal, int Etot) {
    int e = blockIdx.x * blockDim.x + threadIdx.x;
    if (e >= Etot) return;
    int d = (e < Ereal) ? __ldg(dstp + e) : (e - Ereal);
    float ex = __expf(g_ex2[e] - fdec(g_amax2[d]));
    g_ex2[e] = ex;
    atomicAdd(&g_den2[d], ex);
}

// half-warp per edge: 16 float4 = 64 floats
__global__ void k_agg2(const int* __restrict__ srcp, const int* __restrict__ dstp, int Ereal, int Etot) {
    int w = (blockIdx.x * blockDim.x + threadIdx.x) >> 5;
    int lane = threadIdx.x & 31;
    int e = w * 2 + (lane >> 4);
    if (e >= Etot) return;
    int l16 = lane & 15;
    int s, d;
    if (e < Ereal) { s = __ldg(srcp + e); d = __ldg(dstp + e); } else { s = d = e - Ereal; }
    float c = g_ex2[e] / fmaxf(g_den2[d], 1e-16f);
    float4 v = ((const float4*)(g_xp2 + (size_t)s * 64))[l16];
    v.x *= c; v.y *= c; v.z *= c; v.w *= c;
    red4(((float4*)(g_out2 + (size_t)d * 64)) + l16, v);
}

// ---------------- pool: sum out2 per graph + counts (half-warp per node) -----
__global__ void k_pool(const int* __restrict__ batch) {
    int w = (blockIdx.x * blockDim.x + threadIdx.x) >> 5;
    int lane = threadIdx.x & 31;
    int n = w * 2 + (lane >> 4);
    if (n >= NN) return;
    int l16 = lane & 15;
    int b = __ldg(batch + n);
    float4 v = ((const float4*)(g_out2 + (size_t)n * 64))[l16];
    red4(((float4*)g_pool) + b * 16 + l16, v);
    if (l16 == 0) atomicAdd(&g_cnt[b], 1.0f);
}

// ---------------- final: (pool/cnt + b2) @ lin_W + lin_b ---------------------
__global__ void k_final(const float* __restrict__ b2, const float* __restrict__ lin_W,
                        const float* __restrict__ lin_b, float* __restrict__ out) {
    int t = blockIdx.x * blockDim.x + threadIdx.x;
    if (t >= NG * 10) return;
    int g = t / 10, j = t % 10;
    float inv = 1.0f / fmaxf(g_cnt[g], 1.0f);
    float acc = lin_b[j];
    #pragma unroll 8
    for (int c = 0; c < 64; c++)
        acc += (g_pool[g * 64 + c] * inv + b2[c]) * lin_W[c * 10 + j];
    out[t] = acc;
}

// ---------------- host launch -------------------------------------------------
extern "C" void kernel_launch(void* const* d_in, const int* in_sizes, int n_in,
                              void* d_out, int out_size) {
    const float* x        = (const float*)d_in[0];
    const int*   ei       = (const int*)  d_in[1];
    const int*   batch    = (const int*)  d_in[2];
    const float* W1       = (const float*)d_in[3];
    const float* att_src1 = (const float*)d_in[4];
    const float* att_dst1 = (const float*)d_in[5];
    const float* b1       = (const float*)d_in[6];
    const float* W2       = (const float*)d_in[7];
    const float* att_src2 = (const float*)d_in[8];
    const float* att_dst2 = (const float*)d_in[9];
    const float* b2       = (const float*)d_in[10];
    const float* lin_W    = (const float*)d_in[11];
    const float* lin_b    = (const float*)d_in[12];
    float* out = (float*)d_out;

    int E = in_sizes[1] / 2;            // 800000
    int T = E + NN;                     // + self loops
    const int* srcp = ei;
    const int* dstp = ei + E;

    k_init<<<2048, 256>>>();
    k_gemm1<<<(NN + 15) / 16, 192>>>(x, W1);
    k_att1<<<(NN * H1 + 7) / 8, 256>>>(att_src1, att_dst1);
    k_max1<<<(T + 255) / 256, 256>>>(srcp, dstp, E, T);
    k_exp1<<<(T + 255) / 256, 256>>>(dstp, E, T);
    k_agg1<<<(T * 32 + 255) / 256, 256>>>(srcp, dstp, E, T);
    k_bias_elu<<<NN, 192>>>(b1);
    k_gemm2<<<(NN + 31) / 32, 128>>>(W2);
    k_att2<<<(NN + 7) / 8, 256>>>(att_src2, att_dst2);
    k_max2<<<(T + 255) / 256, 256>>>(srcp, dstp, E, T);
    k_exp2<<<(T + 255) / 256, 256>>>(dstp, E, T);
    k_agg2<<<((T + 1) / 2 * 32 + 255) / 256, 256>>>(srcp, dstp, E, T);
    k_pool<<<((NN + 1) / 2 * 32 + 255) / 256, 256>>>(batch);
    k_final<<<10, 128>>>(b2, lin_W, lin_b, out);
}

// round 6
// speedup vs baseline: 1.3780x; 1.3780x over previous
#include <cuda_runtime.h>

// Problem-fixed shapes
#define NN 50000
#define EE 800000
#define TT (EE + NN)      // real edges + self loops
#define H1 3
#define D1 192            // 3 heads x 64
#define D2 64
#define NG 128

// ---------------- scratch (device globals; no runtime allocation) -----------
__device__ float g_xp1[(size_t)NN * D1];   // layer1 lin output
__device__ float g_h1[(size_t)NN * D1];    // elu(agg + b1)
__device__ float g_asrc1[NN * H1];
__device__ float g_adst1[NN * H1];
__device__ float g_xp2[(size_t)NN * D2];
__device__ float g_asrc2[NN];
__device__ float g_adst2[NN];
__device__ float g_pool[NG * D2];
__device__ float g_cnt[NG];
// CSR (rebuilt every call; deterministic content, order-free use)
__device__ int   g_deg[NN];        // degree, then reused as scatter cursor
__device__ int   g_row[NN + 1];    // row offsets
__device__ int   g_csrc[TT];       // src node per CSR slot

// ---------------- helpers ----------------------------------------------------
__device__ __forceinline__ float warp_sum(float s) {
    #pragma unroll
    for (int o = 16; o; o >>= 1) s += __shfl_xor_sync(0xFFFFFFFFu, s, o);
    return s;
}
__device__ __forceinline__ float lrelu(float a) { return fmaxf(a, 0.2f * a); }

// ---------------- init --------------------------------------------------------
__global__ void k_init() {
    int i0 = blockIdx.x * blockDim.x + threadIdx.x;
    int st = gridDim.x * blockDim.x;
    for (int i = i0; i < NN; i += st) g_deg[i] = 1;            // self loop
    for (int i = i0; i < NG * D2; i += st) g_pool[i] = 0.f;
    for (int i = i0; i < NG; i += st) g_cnt[i] = 0.f;
}

// ---------------- CSR build ---------------------------------------------------
__global__ void k_hist(const int* __restrict__ dstp, int E) {
    int e = blockIdx.x * blockDim.x + threadIdx.x;
    if (e < E) atomicAdd(&g_deg[__ldg(dstp + e)], 1);
}

#define SCAN_T 1024
__global__ void k_scan() {   // exclusive prefix of g_deg -> g_row
    __shared__ int sums[SCAN_T];
    int t = threadIdx.x;
    const int chunk = (NN + SCAN_T - 1) / SCAN_T;   // 49
    int b0 = t * chunk, b1 = min(b0 + chunk, NN);
    int s = 0;
    for (int i = b0; i < b1; i++) s += g_deg[i];
    sums[t] = s;
    __syncthreads();
    for (int off = 1; off < SCAN_T; off <<= 1) {
        int v = (t >= off) ? sums[t - off] : 0;
        __syncthreads();
        sums[t] += v;
        __syncthreads();
    }
    int run = sums[t] - s;     // exclusive
    for (int i = b0; i < b1; i++) { g_row[i] = run; run += g_deg[i]; }
    if (t == SCAN_T - 1) g_row[NN] = run;
}

__global__ void k_prep() {     // self-loop slot + cursor init
    int n = blockIdx.x * blockDim.x + threadIdx.x;
    if (n >= NN) return;
    int r = g_row[n];
    g_csrc[r] = n;
    g_deg[n] = r + 1;          // cursor starts after self loop
}

__global__ void k_scatter(const int* __restrict__ srcp, const int* __restrict__ dstp, int E) {
    int e = blockIdx.x * blockDim.x + threadIdx.x;
    if (e >= E) return;
    int pos = atomicAdd(&g_deg[__ldg(dstp + e)], 1);
    g_csrc[pos] = __ldg(srcp + e);
}

// ---------------- GEMM1: xp1 = x @ W1 (16 rows/block, 192 threads) -----------
// shared tile transposed [k][row] so per-k operand fetch is 4 broadcast LDS.128
__global__ void k_gemm1(const float* __restrict__ x, const float* __restrict__ W1) {
    __shared__ float xs[64][20];   // k-chunk 64, 16 rows, pad to 20 (16B aligned rows)
    int t = threadIdx.x;           // 0..191 = output column
    int r0 = blockIdx.x * 16;
    float acc[16];
    #pragma unroll
    for (int r = 0; r < 16; r++) acc[r] = 0.f;

    for (int k0 = 0; k0 < 128; k0 += 64) {
        __syncthreads();
        for (int i = t; i < 16 * 64; i += 192) {
            int c = i & 63, r = i >> 6;
            xs[c][r] = (r0 + r < NN) ? x[(size_t)(r0 + r) * 128 + k0 + c] : 0.f;
        }
        __syncthreads();
        #pragma unroll 8
        for (int kk = 0; kk < 64; kk++) {
            float w = W1[(k0 + kk) * 192 + t];
            float4 a0 = *(const float4*)&xs[kk][0];
            float4 a1 = *(const float4*)&xs[kk][4];
            float4 a2 = *(const float4*)&xs[kk][8];
            float4 a3 = *(const float4*)&xs[kk][12];
            acc[0]  = fmaf(a0.x, w, acc[0]);  acc[1]  = fmaf(a0.y, w, acc[1]);
            acc[2]  = fmaf(a0.z, w, acc[2]);  acc[3]  = fmaf(a0.w, w, acc[3]);
            acc[4]  = fmaf(a1.x, w, acc[4]);  acc[5]  = fmaf(a1.y, w, acc[5]);
            acc[6]  = fmaf(a1.z, w, acc[6]);  acc[7]  = fmaf(a1.w, w, acc[7]);
            acc[8]  = fmaf(a2.x, w, acc[8]);  acc[9]  = fmaf(a2.y, w, acc[9]);
            acc[10] = fmaf(a2.z, w, acc[10]); acc[11] = fmaf(a2.w, w, acc[11]);
            acc[12] = fmaf(a3.x, w, acc[12]); acc[13] = fmaf(a3.y, w, acc[13]);
            acc[14] = fmaf(a3.z, w, acc[14]); acc[15] = fmaf(a3.w, w, acc[15]);
        }
    }
    #pragma unroll
    for (int r = 0; r < 16; r++)
        if (r0 + r < NN) g_xp1[(size_t)(r0 + r) * 192 + t] = acc[r];
}

// ---------------- attention dots, layer 1 (warp per node-head) ----------------
__global__ void k_att1(const float* __restrict__ att_src, const float* __restrict__ att_dst) {
    int idx = blockIdx.x * 8 + (threadIdx.x >> 5);
    if (idx >= NN * H1) return;
    int lane = threadIdx.x & 31;
    int n = idx / 3, h = idx % 3;
    size_t base = (size_t)n * 192 + h * 64;
    float v0 = g_xp1[base + lane], v1 = g_xp1[base + 32 + lane];
    float ss = v0 * att_src[h * 64 + lane] + v1 * att_src[h * 64 + 32 + lane];
    float sd = v0 * att_dst[h * 64 + lane] + v1 * att_dst[h * 64 + 32 + lane];
    ss = warp_sum(ss); sd = warp_sum(sd);
    if (lane == 0) { g_asrc1[idx] = ss; g_adst1[idx] = sd; }
}

// ---------------- fused layer1: softmax(no-max) + aggregate + bias + elu ------
// warp per dst node; lane l owns cols l+32k, k=0..5 (2 cols per head)
__global__ void k_agg1(const float* __restrict__ b1) {
    int d = blockIdx.x * 8 + (threadIdx.x >> 5);
    if (d >= NN) return;
    int lane = threadIdx.x & 31;
    float ad0 = g_adst1[d * 3 + 0], ad1 = g_adst1[d * 3 + 1], ad2 = g_adst1[d * 3 + 2];
    float acc0 = 0.f, acc1 = 0.f, acc2 = 0.f, acc3 = 0.f, acc4 = 0.f, acc5 = 0.f;
    float den0 = 0.f, den1 = 0.f, den2 = 0.f;
    int beg = g_row[d], end = g_row[d + 1];
    for (int j = beg; j < end; j++) {
        int s = __ldg(g_csrc + j);
        float e0 = __expf(lrelu(__ldg(g_asrc1 + s * 3 + 0) + ad0));
        float e1 = __expf(lrelu(__ldg(g_asrc1 + s * 3 + 1) + ad1));
        float e2 = __expf(lrelu(__ldg(g_asrc1 + s * 3 + 2) + ad2));
        den0 += e0; den1 += e1; den2 += e2;
        const float* xr = g_xp1 + (size_t)s * 192 + lane;
        acc0 = fmaf(e0, __ldg(xr),       acc0);
        acc1 = fmaf(e0, __ldg(xr + 32),  acc1);
        acc2 = fmaf(e1, __ldg(xr + 64),  acc2);
        acc3 = fmaf(e1, __ldg(xr + 96),  acc3);
        acc4 = fmaf(e2, __ldg(xr + 128), acc4);
        acc5 = fmaf(e2, __ldg(xr + 160), acc5);
    }
    float i0 = 1.f / fmaxf(den0, 1e-16f);
    float i1 = 1.f / fmaxf(den1, 1e-16f);
    float i2 = 1.f / fmaxf(den2, 1e-16f);
    float* o = g_h1 + (size_t)d * 192 + lane;
    float v;
    v = acc0 * i0 + b1[lane];       o[0]   = v > 0.f ? v : expm1f(v);
    v = acc1 * i0 + b1[lane + 32];  o[32]  = v > 0.f ? v : expm1f(v);
    v = acc2 * i1 + b1[lane + 64];  o[64]  = v > 0.f ? v : expm1f(v);
    v = acc3 * i1 + b1[lane + 96];  o[96]  = v > 0.f ? v : expm1f(v);
    v = acc4 * i2 + b1[lane + 128]; o[128] = v > 0.f ? v : expm1f(v);
    v = acc5 * i2 + b1[lane + 160]; o[160] = v > 0.f ? v : expm1f(v);
}

// ---------------- GEMM2: xp2 = h1 @ W2 (64 rows/block, 256 threads) -----------
__global__ void k_gemm2(const float* __restrict__ W2) {
    __shared__ float xs[64][68];   // k-chunk 64, 64 rows, pad 68 (16B aligned)
    int t = threadIdx.x;
    int col = t & 63, grp = t >> 6;      // grp -> rows [grp*16, grp*16+16)
    int r0 = blockIdx.x * 64;
    float acc[16];
    #pragma unroll
    for (int r = 0; r < 16; r++) acc[r] = 0.f;

    for (int k0 = 0; k0 < 192; k0 += 64) {
        __syncthreads();
        for (int i = t; i < 64 * 64; i += 256) {
            int c = i & 63, r = i >> 6;
            xs[c][r] = (r0 + r < NN) ? g_h1[(size_t)(r0 + r) * 192 + k0 + c] : 0.f;
        }
        __syncthreads();
        #pragma unroll 8
        for (int kk = 0; kk < 64; kk++) {
            float w = W2[(k0 + kk) * 64 + col];
            float4 a0 = *(const float4*)&xs[kk][grp * 16 + 0];
            float4 a1 = *(const float4*)&xs[kk][grp * 16 + 4];
            float4 a2 = *(const float4*)&xs[kk][grp * 16 + 8];
            float4 a3 = *(const float4*)&xs[kk][grp * 16 + 12];
            acc[0]  = fmaf(a0.x, w, acc[0]);  acc[1]  = fmaf(a0.y, w, acc[1]);
            acc[2]  = fmaf(a0.z, w, acc[2]);  acc[3]  = fmaf(a0.w, w, acc[3]);
            acc[4]  = fmaf(a1.x, w, acc[4]);  acc[5]  = fmaf(a1.y, w, acc[5]);
            acc[6]  = fmaf(a1.z, w, acc[6]);  acc[7]  = fmaf(a1.w, w, acc[7]);
            acc[8]  = fmaf(a2.x, w, acc[8]);  acc[9]  = fmaf(a2.y, w, acc[9]);
            acc[10] = fmaf(a2.z, w, acc[10]); acc[11] = fmaf(a2.w, w, acc[11]);
            acc[12] = fmaf(a3.x, w, acc[12]); acc[13] = fmaf(a3.y, w, acc[13]);
            acc[14] = fmaf(a3.z, w, acc[14]); acc[15] = fmaf(a3.w, w, acc[15]);
        }
    }
    #pragma unroll
    for (int r = 0; r < 16; r++) {
        int nr = r0 + grp * 16 + r;
        if (nr < NN) g_xp2[(size_t)nr * 64 + col] = acc[r];
    }
}

// ---------------- attention dots, layer 2 (warp per node) ---------------------
__global__ void k_att2(const float* __restrict__ att_src, const float* __restrict__ att_dst) {
    int n = blockIdx.x * 8 + (threadIdx.x >> 5);
    if (n >= NN) return;
    int lane = threadIdx.x & 31;
    size_t base = (size_t)n * 64;
    float v0 = g_xp2[base + lane], v1 = g_xp2[base + 32 + lane];
    float ss = v0 * att_src[lane] + v1 * att_src[32 + lane];
    float sd = v0 * att_dst[lane] + v1 * att_dst[32 + lane];
    ss = warp_sum(ss); sd = warp_sum(sd);
    if (lane == 0) { g_asrc2[n] = ss; g_adst2[n] = sd; }
}

// ---------------- fused layer2: softmax + aggregate + bias + pool -------------
__global__ void k_agg2(const float* __restrict__ b2, const int* __restrict__ batch) {
    int d = blockIdx.x * 8 + (threadIdx.x >> 5);
    if (d >= NN) return;
    int lane = threadIdx.x & 31;
    float ad = g_adst2[d];
    float acc0 = 0.f, acc1 = 0.f, den = 0.f;
    int beg = g_row[d], end = g_row[d + 1];
    for (int j = beg; j < end; j++) {
        int s = __ldg(g_csrc + j);
        float e = __expf(lrelu(__ldg(g_asrc2 + s) + ad));
        den += e;
        const float* xr = g_xp2 + (size_t)s * 64 + lane;
        acc0 = fmaf(e, __ldg(xr),      acc0);
        acc1 = fmaf(e, __ldg(xr + 32), acc1);
    }
    float inv = 1.f / fmaxf(den, 1e-16f);
    int b = __ldg(batch + d);
    atomicAdd(&g_pool[b * 64 + lane],      acc0 * inv + b2[lane]);
    atomicAdd(&g_pool[b * 64 + lane + 32], acc1 * inv + b2[lane + 32]);
    if (lane == 0) atomicAdd(&g_cnt[b], 1.0f);
}

// ---------------- final: (pool/cnt) @ lin_W + lin_b ---------------------------
__global__ void k_final(const float* __restrict__ lin_W, const float* __restrict__ lin_b,
                        float* __restrict__ out) {
    int t = blockIdx.x * blockDim.x + threadIdx.x;
    if (t >= NG * 10) return;
    int g = t / 10, j = t % 10;
    float inv = 1.0f / fmaxf(g_cnt[g], 1.0f);
    float acc = lin_b[j];
    #pragma unroll 8
    for (int c = 0; c < 64; c++)
        acc += g_pool[g * 64 + c] * inv * lin_W[c * 10 + j];
    out[t] = acc;
}

// ---------------- host launch -------------------------------------------------
extern "C" void kernel_launch(void* const* d_in, const int* in_sizes, int n_in,
                              void* d_out, int out_size) {
    const float* x        = (const float*)d_in[0];
    const int*   ei       = (const int*)  d_in[1];
    const int*   batch    = (const int*)  d_in[2];
    const float* W1       = (const float*)d_in[3];
    const float* att_src1 = (const float*)d_in[4];
    const float* att_dst1 = (const float*)d_in[5];
    const float* b1       = (const float*)d_in[6];
    const float* W2       = (const float*)d_in[7];
    const float* att_src2 = (const float*)d_in[8];
    const float* att_dst2 = (const float*)d_in[9];
    const float* b2       = (const float*)d_in[10];
    const float* lin_W    = (const float*)d_in[11];
    const float* lin_b    = (const float*)d_in[12];
    float* out = (float*)d_out;

    int E = in_sizes[1] / 2;            // 800000
    const int* srcp = ei;
    const int* dstp = ei + E;

    // CSR build (dst-sorted adjacency incl. implicit self loops)
    k_init<<<256, 256>>>();
    k_hist<<<(E + 255) / 256, 256>>>(dstp, E);
    k_scan<<<1, SCAN_T>>>();
    k_prep<<<(NN + 255) / 256, 256>>>();
    k_scatter<<<(E + 255) / 256, 256>>>(srcp, dstp, E);

    // layer 1
    k_gemm1<<<(NN + 15) / 16, 192>>>(x, W1);
    k_att1<<<(NN * H1 + 7) / 8, 256>>>(att_src1, att_dst1);
    k_agg1<<<(NN + 7) / 8, 256>>>(b1);

    // layer 2
    k_gemm2<<<(NN + 63) / 64, 256>>>(W2);
    k_att2<<<(NN + 7) / 8, 256>>>(att_src2, att_dst2);
    k_agg2<<<(NN + 7) / 8, 256>>>(b2, batch);

    // readout
    k_final<<<10, 128>>>(lin_W, lin_b, out);
}